// round 5
// baseline (speedup 1.0000x reference)
#include <cuda_runtime.h>

// GRUExtractor: 2-layer GRU, B=4096, T=256, I=16, H=40, fp32.
// Persistent fused kernel: threads specialize by (layer, gate, unit j),
// weights register-cached, h-state in smem, f32x2 packed FMAs,
// layer-1 pipelined one timestep behind layer-0.

#define HSZ 40
#define ISZ 16
#define TSZ 256
#define NB  4096
#define SLOT_T 256          // threads per slot (padded for clean warps)
#define CTA_T  512          // 2 slots per CTA
#define RMAX 14
#define NSLOTS 296          // 148 CTAs * 2 slots
#define FULLSLOTS 248       // slots with 14 rows; rest have 13 (248*14+48*13=4096)

typedef unsigned long long u64;

__device__ __forceinline__ u64 pk2(float lo, float hi) {
    u64 d; asm("mov.b64 %0,{%1,%2};" : "=l"(d) : "f"(lo), "f"(hi)); return d;
}
__device__ __forceinline__ void upk2(u64 d, float& a, float& b) {
    asm("mov.b64 {%0,%1},%2;" : "=f"(a), "=f"(b) : "l"(d));
}
__device__ __forceinline__ u64 ffma2(u64 a, u64 b, u64 c) {
    u64 d; asm("fma.rn.f32x2 %0,%1,%2,%3;" : "=l"(d) : "l"(a), "l"(b), "l"(c)); return d;
}
__device__ __forceinline__ float hsum2(u64 d) { float a, b; upk2(d, a, b); return a + b; }

__device__ __forceinline__ float sigm(float x) {
    return __fdividef(1.0f, 1.0f + __expf(-x));
}
__device__ __forceinline__ float tanh_f(float x) {
    return __fdividef(2.0f, 1.0f + __expf(-2.0f * x)) - 1.0f;
}

__global__ void __launch_bounds__(CTA_T, 1) gru_fused_kernel(
    const float* __restrict__ x,     // (B, T, I)
    const float* __restrict__ Wih0,  // (120, 16)
    const float* __restrict__ Whh0,  // (120, 40)
    const float* __restrict__ bih0,  // (120)
    const float* __restrict__ bhh0,  // (120)
    const float* __restrict__ Wih1,  // (120, 40)
    const float* __restrict__ Whh1,  // (120, 40)
    const float* __restrict__ bih1,  // (120)
    const float* __restrict__ bhh1,  // (120)
    float* __restrict__ out)         // (B, 40)
{
    // h state + gate exchange buffers (per slot)
    __shared__ __align__(16) float h0s[2][RMAX][HSZ];
    __shared__ __align__(16) float h1s[2][RMAX][HSZ];
    __shared__ __align__(16) float4 gb0[2][RMAX][HSZ];  // {r, z, accx(+bin), acch(+bhn)}
    __shared__ __align__(16) float4 gb1[2][RMAX][HSZ];

    const int tid  = threadIdx.x;
    const int slot = tid >> 8;          // 0 or 1
    const int r    = tid & 255;

    const int slot_id = blockIdx.x * 2 + slot;
    int base, nrows;
    if (slot_id < FULLSLOTS) { base = slot_id * 14; nrows = 14; }
    else { base = FULLSLOTS * 14 + (slot_id - FULLSLOTS) * 13; nrows = 13; }

    const bool isL0 = (r < 120);
    const bool isL1 = (r >= 128 && r < 248);
    const int lr = isL1 ? (r - 128) : r;      // 0..119 within group
    const int g  = lr / 40;                   // gate: 0=r 1=z 2=n
    const int j  = lr % 40;                   // hidden unit
    const int wr = g * 40 + j;                // stacked weight row

    // ---- register-cached weights ----
    // L0: wA = Whh0 row (20 pairs, dot over h0), wB = Wih0 row (8 pairs, dot over x)
    // L1: wA = Wih1 row (20 pairs, dot over h0), wB = Whh1 row (20 pairs, dot over h1)
    u64 wA[20], wB[20];
    float bx = 0.0f, bh = 0.0f;

    if (isL0) {
        const float4* p = (const float4*)(Whh0 + wr * HSZ);
        #pragma unroll
        for (int q = 0; q < 10; q++) {
            float4 v = p[q];
            wA[2*q]   = pk2(v.x, v.y);
            wA[2*q+1] = pk2(v.z, v.w);
        }
        const float4* px = (const float4*)(Wih0 + wr * ISZ);
        #pragma unroll
        for (int q = 0; q < 4; q++) {
            float4 v = px[q];
            wB[2*q]   = pk2(v.x, v.y);
            wB[2*q+1] = pk2(v.z, v.w);
        }
        if (g < 2) { bx = bih0[wr] + bhh0[wr]; bh = 0.0f; }
        else       { bx = bih0[wr];            bh = bhh0[wr]; }
    } else if (isL1) {
        const float4* pi = (const float4*)(Wih1 + wr * HSZ);
        const float4* ph = (const float4*)(Whh1 + wr * HSZ);
        #pragma unroll
        for (int q = 0; q < 10; q++) {
            float4 vi = pi[q];
            wA[2*q]   = pk2(vi.x, vi.y);
            wA[2*q+1] = pk2(vi.z, vi.w);
            float4 vh = ph[q];
            wB[2*q]   = pk2(vh.x, vh.y);
            wB[2*q+1] = pk2(vh.z, vh.w);
        }
        if (g < 2) { bx = bih1[wr] + bhh1[wr]; bh = 0.0f; }
        else       { bx = bih1[wr];            bh = bhh1[wr]; }
    }

    // zero-init h state
    for (int e = r; e < nrows * HSZ; e += SLOT_T) {
        h0s[slot][e / HSZ][e % HSZ] = 0.0f;
        h1s[slot][e / HSZ][e % HSZ] = 0.0f;
    }
    __syncthreads();

    // ---- supersteps: L0 computes t=s, L1 computes t=s-1 (pipelined) ----
    for (int s = 0; s <= TSZ; ++s) {
        // ===== PHASE A: dot products + r/z activations =====
        if (isL0 && s < TSZ) {
            for (int row = 0; row < nrows; ++row) {
                const u64* hp = (const u64*)&h0s[slot][row][0];
                u64 a0 = 0ull, a1 = 0ull;      // h-dot (2-way to shorten chain)
                #pragma unroll
                for (int q = 0; q < 10; q++) {
                    a0 = ffma2(wA[2*q],   hp[2*q],   a0);
                    a1 = ffma2(wA[2*q+1], hp[2*q+1], a1);
                }
                u64 b0 = 0ull;                 // x-dot
                const float4* xp = (const float4*)(x + ((base + row) * TSZ + s) * ISZ);
                #pragma unroll
                for (int q = 0; q < 4; q++) {
                    float4 v = xp[q];
                    b0 = ffma2(wB[2*q],   pk2(v.x, v.y), b0);
                    b0 = ffma2(wB[2*q+1], pk2(v.z, v.w), b0);
                }
                float sH = hsum2(a0) + hsum2(a1);
                float sX = hsum2(b0);
                if (g < 2) {
                    float act = sigm(sX + sH + bx);
                    ((float*)&gb0[slot][row][j])[g] = act;
                } else {
                    ((float2*)&gb0[slot][row][j])[1] = make_float2(sX + bx, sH + bh);
                }
            }
        }
        if (isL1 && s >= 1) {
            for (int row = 0; row < nrows; ++row) {
                const u64* hp0 = (const u64*)&h0s[slot][row][0];
                const u64* hp1 = (const u64*)&h1s[slot][row][0];
                u64 a0 = 0ull, a1 = 0ull;      // input-dot over h0
                u64 c0 = 0ull, c1 = 0ull;      // hidden-dot over h1
                #pragma unroll
                for (int q = 0; q < 10; q++) {
                    a0 = ffma2(wA[2*q],   hp0[2*q],   a0);
                    a1 = ffma2(wA[2*q+1], hp0[2*q+1], a1);
                    c0 = ffma2(wB[2*q],   hp1[2*q],   c0);
                    c1 = ffma2(wB[2*q+1], hp1[2*q+1], c1);
                }
                float sI = hsum2(a0) + hsum2(a1);
                float sH = hsum2(c0) + hsum2(c1);
                if (g < 2) {
                    float act = sigm(sI + sH + bx);
                    ((float*)&gb1[slot][row][j])[g] = act;
                } else {
                    ((float2*)&gb1[slot][row][j])[1] = make_float2(sI + bx, sH + bh);
                }
            }
        }
        __syncthreads();

        // ===== PHASE B: n activation + state update (n-gate threads) =====
        if (isL0 && g == 2 && s < TSZ) {
            for (int row = 0; row < nrows; ++row) {
                float4 gv = gb0[slot][row][j];
                float n = tanh_f(gv.z + gv.x * gv.w);
                float hold = h0s[slot][row][j];
                h0s[slot][row][j] = n + gv.y * (hold - n);
            }
        }
        if (isL1 && g == 2 && s >= 1) {
            for (int row = 0; row < nrows; ++row) {
                float4 gv = gb1[slot][row][j];
                float n = tanh_f(gv.z + gv.x * gv.w);
                float hold = h1s[slot][row][j];
                h1s[slot][row][j] = n + gv.y * (hold - n);
            }
        }
        __syncthreads();
    }

    // ---- write final layer-1 hidden state ----
    for (int e = r; e < nrows * HSZ; e += SLOT_T) {
        int row = e / HSZ, jj = e % HSZ;
        out[(base + row) * HSZ + jj] = h1s[slot][row][jj];
    }
}

extern "C" void kernel_launch(void* const* d_in, const int* in_sizes, int n_in,
                              void* d_out, int out_size) {
    const float* x    = (const float*)d_in[0];
    const float* Wih0 = (const float*)d_in[1];
    const float* Whh0 = (const float*)d_in[2];
    const float* bih0 = (const float*)d_in[3];
    const float* bhh0 = (const float*)d_in[4];
    const float* Wih1 = (const float*)d_in[5];
    const float* Whh1 = (const float*)d_in[6];
    const float* bih1 = (const float*)d_in[7];
    const float* bhh1 = (const float*)d_in[8];
    float* out = (float*)d_out;

    gru_fused_kernel<<<148, CTA_T>>>(x, Wih0, Whh0, bih0, bhh0,
                                     Wih1, Whh1, bih1, bhh1, out);
}

// round 6
// speedup vs baseline: 1.0650x; 1.0650x over previous
#include <cuda_runtime.h>

// GRUExtractor: 2-layer GRU, B=4096, T=256, I=16, H=40, fp32.
// Persistent fused kernel, threads specialize by (layer, gate, unit j).
// R6: unrolled row loops (uniform 14 rows/slot w/ clamp), float4 h loads,
//     x prefetch via idle threads into smem double-buffer, per-slot named
//     barriers, SoA gate exchange.

#define HSZ 40
#define ISZ 16
#define TSZ 256
#define NB  4096
#define NR  14
#define SLOT_T 256
#define CTA_T  512

typedef unsigned long long u64;

__device__ __forceinline__ u64 pk2(float lo, float hi) {
    u64 d; asm("mov.b64 %0,{%1,%2};" : "=l"(d) : "f"(lo), "f"(hi)); return d;
}
__device__ __forceinline__ void upk2(u64 d, float& a, float& b) {
    asm("mov.b64 {%0,%1},%2;" : "=f"(a), "=f"(b) : "l"(d));
}
__device__ __forceinline__ u64 ffma2(u64 a, u64 b, u64 c) {
    u64 d; asm("fma.rn.f32x2 %0,%1,%2,%3;" : "=l"(d) : "l"(a), "l"(b), "l"(c)); return d;
}
__device__ __forceinline__ float hsum2(u64 d) { float a, b; upk2(d, a, b); return a + b; }

__device__ __forceinline__ float sigm(float x) {
    return __fdividef(1.0f, 1.0f + __expf(-x));
}
__device__ __forceinline__ float tanh_f(float x) {
    return __fdividef(2.0f, 1.0f + __expf(-2.0f * x)) - 1.0f;
}

__device__ __forceinline__ void slot_bar(int slot) {
    asm volatile("bar.sync %0, %1;" :: "r"(slot + 1), "r"(SLOT_T) : "memory");
}

__global__ void __launch_bounds__(CTA_T, 1) gru_fused_kernel(
    const float* __restrict__ x,     // (B, T, I)
    const float* __restrict__ Wih0,  // (120, 16)
    const float* __restrict__ Whh0,  // (120, 40)
    const float* __restrict__ bih0,  // (120)
    const float* __restrict__ bhh0,  // (120)
    const float* __restrict__ Wih1,  // (120, 40)
    const float* __restrict__ Whh1,  // (120, 40)
    const float* __restrict__ bih1,  // (120)
    const float* __restrict__ bhh1,  // (120)
    float* __restrict__ out)         // (B, 40)
{
    __shared__ __align__(16) float h0s[2][NR][HSZ];
    __shared__ __align__(16) float h1s[2][NR][HSZ];
    // SoA gate exchange: [slot][layer][row][j]
    __shared__ __align__(16) float ras[2][2][NR][HSZ];
    __shared__ __align__(16) float zas[2][2][NR][HSZ];
    __shared__ __align__(16) float nxs[2][2][NR][HSZ];
    __shared__ __align__(16) float nhs[2][2][NR][HSZ];
    // x stage: [slot][parity][row][chunk of 4 floats]
    __shared__ __align__(16) float4 xbs[2][2][NR][ISZ / 4];

    const int tid  = threadIdx.x;
    const int slot = tid >> 8;
    const int r    = tid & 255;

    const int slot_id = blockIdx.x * 2 + slot;
    const int base = slot_id * NR;

    const bool isL0 = (r < 120);
    const bool isL1 = (r >= 128 && r < 248);
    const int  lay  = isL1 ? 1 : 0;
    const int  lr   = isL1 ? (r - 128) : r;
    const int  g    = lr / 40;
    const int  j    = lr % 40;
    const int  wr   = g * 40 + j;

    int pf = -1;                      // x-prefetch lane id 0..15
    if (r >= 120 && r < 128) pf = r - 120;
    else if (r >= 248)       pf = r - 240;

    float (*h0)[HSZ] = h0s[slot];
    float (*h1)[HSZ] = h1s[slot];
    float (*Ra)[HSZ] = ras[slot][lay];
    float (*Za)[HSZ] = zas[slot][lay];
    float (*Nx)[HSZ] = nxs[slot][lay];
    float (*Nh)[HSZ] = nhs[slot][lay];

    // ---- register-cached weights ----
    u64 wA[20], wB[20];
    float bx = 0.0f, bh = 0.0f;

    if (isL0) {
        const float4* p = (const float4*)(Whh0 + wr * HSZ);
        #pragma unroll
        for (int q = 0; q < 10; q++) {
            float4 v = p[q];
            wA[2*q]   = pk2(v.x, v.y);
            wA[2*q+1] = pk2(v.z, v.w);
        }
        const float4* px = (const float4*)(Wih0 + wr * ISZ);
        #pragma unroll
        for (int q = 0; q < 4; q++) {
            float4 v = px[q];
            wB[2*q]   = pk2(v.x, v.y);
            wB[2*q+1] = pk2(v.z, v.w);
        }
        if (g < 2) { bx = bih0[wr] + bhh0[wr]; bh = 0.0f; }
        else       { bx = bih0[wr];            bh = bhh0[wr]; }
    } else if (isL1) {
        const float4* pi = (const float4*)(Wih1 + wr * HSZ);
        const float4* ph = (const float4*)(Whh1 + wr * HSZ);
        #pragma unroll
        for (int q = 0; q < 10; q++) {
            float4 vi = pi[q];
            wA[2*q]   = pk2(vi.x, vi.y);
            wA[2*q+1] = pk2(vi.z, vi.w);
            float4 vh = ph[q];
            wB[2*q]   = pk2(vh.x, vh.y);
            wB[2*q+1] = pk2(vh.z, vh.w);
        }
        if (g < 2) { bx = bih1[wr] + bhh1[wr]; bh = 0.0f; }
        else       { bx = bih1[wr];            bh = bhh1[wr]; }
    }

    // ---- init: zero h, prefetch x(t=0) ----
    for (int e = r; e < NR * HSZ; e += SLOT_T) {
        h0[e / HSZ][e % HSZ] = 0.0f;
        h1[e / HSZ][e % HSZ] = 0.0f;
    }
    if (pf >= 0) {
        const float4* xg = (const float4*)x;
        #pragma unroll
        for (int k = 0; k < 4; k++) {
            int idx = pf + 16 * k;
            if (idx < NR * 4) {
                int row = idx >> 2, c = idx & 3;
                int gr = base + row; if (gr > NB - 1) gr = NB - 1;
                xbs[slot][0][row][c] = xg[(gr * TSZ + 0) * 4 + c];
            }
        }
    }
    __syncthreads();

    // ---- supersteps: L0 computes t=s, L1 computes t=s-1 ----
    for (int s = 0; s <= TSZ; ++s) {
        // x prefetch for s+1 (idle threads)
        if (pf >= 0) {
            int s1 = s + 1;
            if (s1 < TSZ) {
                const float4* xg = (const float4*)x;
                #pragma unroll
                for (int k = 0; k < 4; k++) {
                    int idx = pf + 16 * k;
                    if (idx < NR * 4) {
                        int row = idx >> 2, c = idx & 3;
                        int gr = base + row; if (gr > NB - 1) gr = NB - 1;
                        xbs[slot][s1 & 1][row][c] = xg[(gr * TSZ + s1) * 4 + c];
                    }
                }
            }
        }

        // ===== PHASE A: dot products + r/z activations =====
        if (isL0 && s < TSZ) {
            #pragma unroll 7
            for (int row = 0; row < NR; ++row) {
                const float4* hp = (const float4*)h0[row];
                u64 a0 = 0ull, a1 = 0ull;
                #pragma unroll
                for (int q = 0; q < 5; q++) {
                    float4 v0 = hp[2*q], v1 = hp[2*q+1];
                    a0 = ffma2(wA[4*q],   pk2(v0.x, v0.y), a0);
                    a1 = ffma2(wA[4*q+1], pk2(v0.z, v0.w), a1);
                    a0 = ffma2(wA[4*q+2], pk2(v1.x, v1.y), a0);
                    a1 = ffma2(wA[4*q+3], pk2(v1.z, v1.w), a1);
                }
                const float4* xp = xbs[slot][s & 1][row];
                u64 b0 = 0ull, b1 = 0ull;
                #pragma unroll
                for (int q = 0; q < 2; q++) {
                    float4 v0 = xp[2*q], v1 = xp[2*q+1];
                    b0 = ffma2(wB[4*q],   pk2(v0.x, v0.y), b0);
                    b1 = ffma2(wB[4*q+1], pk2(v0.z, v0.w), b1);
                    b0 = ffma2(wB[4*q+2], pk2(v1.x, v1.y), b0);
                    b1 = ffma2(wB[4*q+3], pk2(v1.z, v1.w), b1);
                }
                float sH = hsum2(a0) + hsum2(a1);
                float sX = hsum2(b0) + hsum2(b1);
                if (g == 0)      Ra[row][j] = sigm(sX + sH + bx);
                else if (g == 1) Za[row][j] = sigm(sX + sH + bx);
                else { Nx[row][j] = sX + bx; Nh[row][j] = sH + bh; }
            }
        }
        if (isL1 && s >= 1) {
            #pragma unroll 7
            for (int row = 0; row < NR; ++row) {
                const float4* hp0 = (const float4*)h0[row];
                const float4* hp1 = (const float4*)h1[row];
                u64 a0 = 0ull, a1 = 0ull, c0 = 0ull, c1 = 0ull;
                #pragma unroll
                for (int q = 0; q < 5; q++) {
                    float4 u0 = hp0[2*q], u1 = hp0[2*q+1];
                    float4 v0 = hp1[2*q], v1 = hp1[2*q+1];
                    a0 = ffma2(wA[4*q],   pk2(u0.x, u0.y), a0);
                    a1 = ffma2(wA[4*q+1], pk2(u0.z, u0.w), a1);
                    a0 = ffma2(wA[4*q+2], pk2(u1.x, u1.y), a0);
                    a1 = ffma2(wA[4*q+3], pk2(u1.z, u1.w), a1);
                    c0 = ffma2(wB[4*q],   pk2(v0.x, v0.y), c0);
                    c1 = ffma2(wB[4*q+1], pk2(v0.z, v0.w), c1);
                    c0 = ffma2(wB[4*q+2], pk2(v1.x, v1.y), c0);
                    c1 = ffma2(wB[4*q+3], pk2(v1.z, v1.w), c1);
                }
                float sI = hsum2(a0) + hsum2(a1);
                float sH = hsum2(c0) + hsum2(c1);
                if (g == 0)      Ra[row][j] = sigm(sI + sH + bx);
                else if (g == 1) Za[row][j] = sigm(sI + sH + bx);
                else { Nx[row][j] = sI + bx; Nh[row][j] = sH + bh; }
            }
        }
        slot_bar(slot);

        // ===== PHASE B: n activation + state update (g==2 threads) =====
        if (g == 2) {
            if (isL0 && s < TSZ) {
                #pragma unroll
                for (int row = 0; row < NR; ++row) {
                    float rr = Ra[row][j], zz = Za[row][j];
                    float xn = Nx[row][j], hn = Nh[row][j];
                    float n = tanh_f(fmaf(rr, hn, xn));
                    float ho = h0[row][j];
                    h0[row][j] = fmaf(zz, ho - n, n);
                }
            } else if (isL1 && s >= 1) {
                #pragma unroll
                for (int row = 0; row < NR; ++row) {
                    float rr = Ra[row][j], zz = Za[row][j];
                    float xn = Nx[row][j], hn = Nh[row][j];
                    float n = tanh_f(fmaf(rr, hn, xn));
                    float ho = h1[row][j];
                    h1[row][j] = fmaf(zz, ho - n, n);
                }
            }
        }
        slot_bar(slot);
    }

    // ---- write final layer-1 hidden state (dup rows write identical data) ----
    for (int e = r; e < NR * HSZ; e += SLOT_T) {
        int row = e / HSZ, jj = e % HSZ;
        int gr = base + row; if (gr > NB - 1) gr = NB - 1;
        out[gr * HSZ + jj] = h1[row][jj];
    }
}

extern "C" void kernel_launch(void* const* d_in, const int* in_sizes, int n_in,
                              void* d_out, int out_size) {
    const float* x    = (const float*)d_in[0];
    const float* Wih0 = (const float*)d_in[1];
    const float* Whh0 = (const float*)d_in[2];
    const float* bih0 = (const float*)d_in[3];
    const float* bhh0 = (const float*)d_in[4];
    const float* Wih1 = (const float*)d_in[5];
    const float* Whh1 = (const float*)d_in[6];
    const float* bih1 = (const float*)d_in[7];
    const float* bhh1 = (const float*)d_in[8];
    float* out = (float*)d_out;

    gru_fused_kernel<<<148, CTA_T>>>(x, Wih0, Whh0, bih0, bhh0,
                                     Wih1, Whh1, bih1, bhh1, out);
}

// round 8
// speedup vs baseline: 1.1664x; 1.0952x over previous
#include <cuda_runtime.h>

// GRUExtractor: 2-layer GRU, B=4096, T=256, I=16, H=40, fp32.
// R8 == R7 resubmit (prior bench was an infra failure, kernel never ran):
// ulonglong2 smem loads (no pk2 MOVs), Phase-B update spread across all
// slot threads, x prefetch via idle threads, per-slot named barriers, SoA.

#define HSZ 40
#define ISZ 16
#define TSZ 256
#define NB  4096
#define NR  14
#define SLOT_T 256
#define CTA_T  512

typedef unsigned long long u64;
typedef ulonglong2 u64x2;

__device__ __forceinline__ void upk2(u64 d, float& a, float& b) {
    asm("mov.b64 {%0,%1},%2;" : "=f"(a), "=f"(b) : "l"(d));
}
__device__ __forceinline__ u64 ffma2(u64 a, u64 b, u64 c) {
    u64 d; asm("fma.rn.f32x2 %0,%1,%2,%3;" : "=l"(d) : "l"(a), "l"(b), "l"(c)); return d;
}
__device__ __forceinline__ float hsum2(u64 d) { float a, b; upk2(d, a, b); return a + b; }

__device__ __forceinline__ float sigm(float x) {
    return __fdividef(1.0f, 1.0f + __expf(-x));
}
__device__ __forceinline__ float tanh_f(float x) {
    return __fdividef(2.0f, 1.0f + __expf(-2.0f * x)) - 1.0f;
}

__device__ __forceinline__ void slot_bar(int slot) {
    asm volatile("bar.sync %0, %1;" :: "r"(slot + 1), "r"(SLOT_T) : "memory");
}

__global__ void __launch_bounds__(CTA_T, 1) gru_fused_kernel(
    const float* __restrict__ x,     // (B, T, I)
    const float* __restrict__ Wih0,  // (120, 16)
    const float* __restrict__ Whh0,  // (120, 40)
    const float* __restrict__ bih0,  // (120)
    const float* __restrict__ bhh0,  // (120)
    const float* __restrict__ Wih1,  // (120, 40)
    const float* __restrict__ Whh1,  // (120, 40)
    const float* __restrict__ bih1,  // (120)
    const float* __restrict__ bhh1,  // (120)
    float* __restrict__ out)         // (B, 40)
{
    __shared__ __align__(16) float h0s[2][NR][HSZ];
    __shared__ __align__(16) float h1s[2][NR][HSZ];
    // SoA gate exchange: [slot][layer][row][j]
    __shared__ __align__(16) float ras[2][2][NR][HSZ];
    __shared__ __align__(16) float zas[2][2][NR][HSZ];
    __shared__ __align__(16) float nxs[2][2][NR][HSZ];
    __shared__ __align__(16) float nhs[2][2][NR][HSZ];
    // x stage: [slot][parity][row][chunk of 4 floats]
    __shared__ __align__(16) float4 xbs[2][2][NR][ISZ / 4];

    const int tid  = threadIdx.x;
    const int slot = tid >> 8;
    const int r    = tid & 255;

    const int slot_id = blockIdx.x * 2 + slot;
    const int base = slot_id * NR;

    const bool isL0 = (r < 120);
    const bool isL1 = (r >= 128 && r < 248);
    const int  lay  = isL1 ? 1 : 0;
    const int  lr   = isL1 ? (r - 128) : r;
    const int  g    = lr / 40;
    const int  j    = lr % 40;
    const int  wr   = g * 40 + j;

    int pf = -1;                      // x-prefetch lane id 0..15
    if (r >= 120 && r < 128) pf = r - 120;
    else if (r >= 248)       pf = r - 240;

    float (*h0)[HSZ] = h0s[slot];
    float (*h1)[HSZ] = h1s[slot];
    float (*Ra)[HSZ] = ras[slot][lay];
    float (*Za)[HSZ] = zas[slot][lay];
    float (*Nx)[HSZ] = nxs[slot][lay];
    float (*Nh)[HSZ] = nhs[slot][lay];

    // ---- register-cached weights (loaded as u64 pairs, no repacking) ----
    u64 wA[20], wB[20];
    float bx = 0.0f, bh = 0.0f;

    if (isL0) {
        const u64x2* p = (const u64x2*)(Whh0 + wr * HSZ);
        #pragma unroll
        for (int q = 0; q < 10; q++) { u64x2 v = p[q]; wA[2*q] = v.x; wA[2*q+1] = v.y; }
        const u64x2* px = (const u64x2*)(Wih0 + wr * ISZ);
        #pragma unroll
        for (int q = 0; q < 4; q++) { u64x2 v = px[q]; wB[2*q] = v.x; wB[2*q+1] = v.y; }
        if (g < 2) { bx = bih0[wr] + bhh0[wr]; bh = 0.0f; }
        else       { bx = bih0[wr];            bh = bhh0[wr]; }
    } else if (isL1) {
        const u64x2* pi = (const u64x2*)(Wih1 + wr * HSZ);
        const u64x2* ph = (const u64x2*)(Whh1 + wr * HSZ);
        #pragma unroll
        for (int q = 0; q < 10; q++) {
            u64x2 vi = pi[q]; wA[2*q] = vi.x; wA[2*q+1] = vi.y;
            u64x2 vh = ph[q]; wB[2*q] = vh.x; wB[2*q+1] = vh.y;
        }
        if (g < 2) { bx = bih1[wr] + bhh1[wr]; bh = 0.0f; }
        else       { bx = bih1[wr];            bh = bhh1[wr]; }
    }

    // ---- init: zero h, prefetch x(t=0) ----
    for (int e = r; e < NR * HSZ; e += SLOT_T) {
        h0[e / HSZ][e % HSZ] = 0.0f;
        h1[e / HSZ][e % HSZ] = 0.0f;
    }
    if (pf >= 0) {
        const float4* xg = (const float4*)x;
        #pragma unroll
        for (int k = 0; k < 4; k++) {
            int idx = pf + 16 * k;
            if (idx < NR * 4) {
                int row = idx >> 2, c = idx & 3;
                int gr = base + row; if (gr > NB - 1) gr = NB - 1;
                xbs[slot][0][row][c] = xg[(gr * TSZ + 0) * 4 + c];
            }
        }
    }
    __syncthreads();

    // ---- supersteps: L0 computes t=s, L1 computes t=s-1 ----
    for (int s = 0; s <= TSZ; ++s) {
        // x prefetch for s+1 (idle threads)
        if (pf >= 0) {
            int s1 = s + 1;
            if (s1 < TSZ) {
                const float4* xg = (const float4*)x;
                #pragma unroll
                for (int k = 0; k < 4; k++) {
                    int idx = pf + 16 * k;
                    if (idx < NR * 4) {
                        int row = idx >> 2, c = idx & 3;
                        int gr = base + row; if (gr > NB - 1) gr = NB - 1;
                        xbs[slot][s1 & 1][row][c] = xg[(gr * TSZ + s1) * 4 + c];
                    }
                }
            }
        }

        // ===== PHASE A: dot products + r/z activations =====
        if (isL0 && s < TSZ) {
            #pragma unroll 7
            for (int row = 0; row < NR; ++row) {
                const u64x2* hp = (const u64x2*)h0[row];
                u64 a0 = 0ull, a1 = 0ull;
                #pragma unroll
                for (int q = 0; q < 5; q++) {
                    u64x2 v0 = hp[2*q], v1 = hp[2*q+1];
                    a0 = ffma2(wA[4*q],   v0.x, a0);
                    a1 = ffma2(wA[4*q+1], v0.y, a1);
                    a0 = ffma2(wA[4*q+2], v1.x, a0);
                    a1 = ffma2(wA[4*q+3], v1.y, a1);
                }
                const u64x2* xp = (const u64x2*)xbs[slot][s & 1][row];
                u64 b0 = 0ull, b1 = 0ull;
                #pragma unroll
                for (int q = 0; q < 2; q++) {
                    u64x2 v0 = xp[2*q], v1 = xp[2*q+1];
                    b0 = ffma2(wB[4*q],   v0.x, b0);
                    b1 = ffma2(wB[4*q+1], v0.y, b1);
                    b0 = ffma2(wB[4*q+2], v1.x, b0);
                    b1 = ffma2(wB[4*q+3], v1.y, b1);
                }
                float sH = hsum2(a0) + hsum2(a1);
                float sX = hsum2(b0) + hsum2(b1);
                if (g == 0)      Ra[row][j] = sigm(sX + sH + bx);
                else if (g == 1) Za[row][j] = sigm(sX + sH + bx);
                else { Nx[row][j] = sX + bx; Nh[row][j] = sH + bh; }
            }
        }
        if (isL1 && s >= 1) {
            #pragma unroll 7
            for (int row = 0; row < NR; ++row) {
                const u64x2* hp0 = (const u64x2*)h0[row];
                const u64x2* hp1 = (const u64x2*)h1[row];
                u64 a0 = 0ull, a1 = 0ull, c0 = 0ull, c1 = 0ull;
                #pragma unroll
                for (int q = 0; q < 5; q++) {
                    u64x2 u0 = hp0[2*q], u1 = hp0[2*q+1];
                    u64x2 v0 = hp1[2*q], v1 = hp1[2*q+1];
                    a0 = ffma2(wA[4*q],   u0.x, a0);
                    a1 = ffma2(wA[4*q+1], u0.y, a1);
                    a0 = ffma2(wA[4*q+2], u1.x, a0);
                    a1 = ffma2(wA[4*q+3], u1.y, a1);
                    c0 = ffma2(wB[4*q],   v0.x, c0);
                    c1 = ffma2(wB[4*q+1], v0.y, c1);
                    c0 = ffma2(wB[4*q+2], v1.x, c0);
                    c1 = ffma2(wB[4*q+3], v1.y, c1);
                }
                float sI = hsum2(a0) + hsum2(a1);
                float sH = hsum2(c0) + hsum2(c1);
                if (g == 0)      Ra[row][j] = sigm(sI + sH + bx);
                else if (g == 1) Za[row][j] = sigm(sI + sH + bx);
                else { Nx[row][j] = sI + bx; Nh[row][j] = sH + bh; }
            }
        }
        slot_bar(slot);

        // ===== PHASE B: h update, spread over ALL slot threads =====
        // 1120 tasks = 2 layers * 14 rows * 40 units
        #pragma unroll
        for (int k = 0; k < 5; k++) {
            int task = r + SLOT_T * k;
            if (task < 2 * NR * HSZ) {
                int lay_t = task / (NR * HSZ);
                int rem   = task - lay_t * (NR * HSZ);
                int row   = rem / HSZ;
                int jj    = rem - row * HSZ;
                bool ok = lay_t == 0 ? (s < TSZ) : (s >= 1);
                if (ok) {
                    float rr = ras[slot][lay_t][row][jj];
                    float zz = zas[slot][lay_t][row][jj];
                    float xn = nxs[slot][lay_t][row][jj];
                    float hn = nhs[slot][lay_t][row][jj];
                    float n  = tanh_f(fmaf(rr, hn, xn));
                    float* hp = lay_t == 0 ? &h0[row][jj] : &h1[row][jj];
                    float ho = *hp;
                    *hp = fmaf(zz, ho - n, n);
                }
            }
        }
        slot_bar(slot);
    }

    // ---- write final layer-1 hidden state (dup rows write identical data) ----
    for (int e = r; e < NR * HSZ; e += SLOT_T) {
        int row = e / HSZ, jj = e % HSZ;
        int gr = base + row; if (gr > NB - 1) gr = NB - 1;
        out[gr * HSZ + jj] = h1[row][jj];
    }
}

extern "C" void kernel_launch(void* const* d_in, const int* in_sizes, int n_in,
                              void* d_out, int out_size) {
    const float* x    = (const float*)d_in[0];
    const float* Wih0 = (const float*)d_in[1];
    const float* Whh0 = (const float*)d_in[2];
    const float* bih0 = (const float*)d_in[3];
    const float* bhh0 = (const float*)d_in[4];
    const float* Wih1 = (const float*)d_in[5];
    const float* Whh1 = (const float*)d_in[6];
    const float* bih1 = (const float*)d_in[7];
    const float* bhh1 = (const float*)d_in[8];
    float* out = (float*)d_out;

    gru_fused_kernel<<<148, CTA_T>>>(x, Wih0, Whh0, bih0, bhh0,
                                     Wih1, Whh1, bih1, bhh1, out);
}